// round 9
// baseline (speedup 1.0000x reference)
#include <cuda_runtime.h>
#include <math.h>
#include <stdint.h>

#define BB  32
#define NN  1024
#define FIN 6
#define F1  128
#define F2  512
#define F3  1024
#define CLS 40

#define TBM 128
#define TBN 128
#define TBK 16
#define TPAD 8

// ---------------- scratch (static __device__ — no allocation allowed) ----------------
__device__ float g_A   [(size_t)BB * NN * NN];   // adjacency exp(-d2), 128 MB
__device__ float g_feat[(size_t)BB * NN * F3];
__device__ float g_mid [(size_t)BB * NN * F2];
__device__ float g_t1  [(size_t)BB * NN * F2];
__device__ float g_t2  [(size_t)BB * NN * F2];
__device__ float g_sq  [BB * NN];
__device__ float g_dis [BB * NN];
__device__ float g_pool[BB * F3];
__device__ float g_fc1 [BB * 512];
__device__ float g_fc2 [BB * 128];

// ---------------- tf32 helpers ----------------
__device__ __forceinline__ uint32_t to_tf32(float x) {
    uint32_t r;
    asm("cvt.rna.tf32.f32 %0, %1;" : "=r"(r) : "f"(x));
    return r;
}
__device__ __forceinline__ void mma_tf32(float* c, const uint32_t* a, const uint32_t* b) {
    asm volatile(
        "mma.sync.aligned.m16n8k8.row.col.f32.tf32.tf32.f32 "
        "{%0,%1,%2,%3}, {%4,%5,%6,%7}, {%8,%9}, {%0,%1,%2,%3};"
        : "+f"(c[0]), "+f"(c[1]), "+f"(c[2]), "+f"(c[3])
        : "r"(a[0]), "r"(a[1]), "r"(a[2]), "r"(a[3]), "r"(b[0]), "r"(b[1]));
}

// ---------------- row squared-norms ----------------
__global__ void rowsq_kernel(const float* __restrict__ x, float* __restrict__ sq, int F) {
    int row  = blockIdx.x * (blockDim.x / 32) + (threadIdx.x >> 5);
    int lane = threadIdx.x & 31;
    if (row >= BB * NN) return;
    const float* p = x + (size_t)row * F;
    float s = 0.f;
    for (int f = lane; f < F; f += 32) { float v = p[f]; s += v * v; }
    #pragma unroll
    for (int o = 16; o; o >>= 1) s += __shfl_down_sync(0xffffffffu, s, o);
    if (lane == 0) sq[row] = s;
}

// ---------------- SIMT gram (F=6): A = exp(2<x_n,x_m> - sq_n - sq_m) ----------------
__global__ void gram_exp_kernel(const float* __restrict__ X, const float* __restrict__ sq,
                                float* __restrict__ Aout, int F) {
    int b = blockIdx.z;
    const float* Xb  = X    + (size_t)b * NN * F;
    float*       Ab  = Aout + (size_t)b * NN * NN;
    const float* sqb = sq   + b * NN;

    int row0 = blockIdx.y * 64, col0 = blockIdx.x * 64;
    __shared__ float As[16][65];
    __shared__ float Bs[16][65];
    int tid = threadIdx.y * 16 + threadIdx.x;

    float acc[4][4];
    #pragma unroll
    for (int i = 0; i < 4; i++)
        #pragma unroll
        for (int j = 0; j < 4; j++) acc[i][j] = 0.f;

    for (int k0 = 0; k0 < F; k0 += 16) {
        #pragma unroll
        for (int t = 0; t < 4; t++) {
            int e = tid + t * 256;
            int r = e >> 4, k = e & 15;
            int kk = k0 + k;
            As[k][r] = (kk < F) ? Xb[(size_t)(row0 + r) * F + kk] : 0.f;
        }
        #pragma unroll
        for (int t = 0; t < 4; t++) {
            int e = tid + t * 256;
            int c = e >> 4, k = e & 15;
            int kk = k0 + k;
            Bs[k][c] = (kk < F) ? Xb[(size_t)(col0 + c) * F + kk] : 0.f;
        }
        __syncthreads();
        #pragma unroll
        for (int k = 0; k < 16; k++) {
            float a[4], bv[4];
            #pragma unroll
            for (int i = 0; i < 4; i++) a[i]  = As[k][threadIdx.y * 4 + i];
            #pragma unroll
            for (int j = 0; j < 4; j++) bv[j] = Bs[k][threadIdx.x * 4 + j];
            #pragma unroll
            for (int i = 0; i < 4; i++)
                #pragma unroll
                for (int j = 0; j < 4; j++) acc[i][j] += a[i] * bv[j];
        }
        __syncthreads();
    }

    #pragma unroll
    for (int i = 0; i < 4; i++) {
        int r = row0 + threadIdx.y * 4 + i;
        float sr = sqb[r];
        #pragma unroll
        for (int j = 0; j < 4; j++) {
            int c = col0 + threadIdx.x * 4 + j;
            Ab[(size_t)r * NN + c] = expf(2.f * acc[i][j] - sr - sqb[c]);
        }
    }
}

// ---------------- dis[b,n] = 1/sqrt(sum_m A[b,n,m]) — float4 reads ----------------
__global__ void deg_kernel(const float* __restrict__ A, float* __restrict__ dis) {
    int row  = blockIdx.x * (blockDim.x / 32) + (threadIdx.x >> 5);
    int lane = threadIdx.x & 31;
    if (row >= BB * NN) return;
    const float4* p = (const float4*)(A + (size_t)row * NN);
    float s = 0.f;
    for (int m = lane; m < NN / 4; m += 32) {
        float4 v = p[m];
        s += v.x + v.y + v.z + v.w;
    }
    #pragma unroll
    for (int o = 16; o; o >>= 1) s += __shfl_down_sync(0xffffffffu, s, o);
    if (lane == 0) dis[row] = 1.f / sqrtf(s);
}

// ---------------- tf32 tensor-core GEMM (R7 engine + folded normalization) ----------
// acc = A @ B'  where B' = (dvec ? diag(dvec) : I) @ B
// epilogue:
//   expmode: C = exp(2*acc - sq_r - sq_c)
//   else:    C = (rs ? rs[r] : 1)*alpha*acc + beta*Cin + beta2*Cin2 + bias, opt. relu
// A: [1024, K] rm.  B normal: [K, Nc] rm; transB: [Nc=1024, K] rm.  K % 16 == 0.
__global__ __launch_bounds__(256) void tgemm_kernel(
    const float* __restrict__ A, const float* __restrict__ B,
    const float* __restrict__ Cin, const float* __restrict__ Cin2,
    const float* __restrict__ bias,
    const float* __restrict__ sqv, const float* __restrict__ rs,
    const float* __restrict__ dvec,
    float* __restrict__ C,
    int Nc, int K,
    long long sA, long long sB, long long sCin, long long sCin2, long long sC,
    float alpha, float beta, float beta2, int relu, int expmode, int transB)
{
    int bz = blockIdx.z;
    A += (size_t)bz * sA;
    B += (size_t)bz * sB;
    C += (size_t)bz * sC;
    if (Cin)  Cin  += (size_t)bz * sCin;
    if (Cin2) Cin2 += (size_t)bz * sCin2;
    const float* sqb = sqv  ? (sqv  + (size_t)bz * NN) : nullptr;
    const float* rsb = rs   ? (rs   + (size_t)bz * NN) : nullptr;
    const float* dv  = dvec ? (dvec + (size_t)bz * NN) : nullptr;

    int row0 = blockIdx.y * TBM, col0 = blockIdx.x * TBN;

    __shared__ float As[2][TBK][TBM + TPAD];
    __shared__ float Bs[2][TBK][TBN + TPAD];

    int tid  = threadIdx.x;
    int lane = tid & 31;
    int warp = tid >> 5;
    int wrow = (warp >> 1) * 32;   // 4 warps along m, 32 rows each
    int wcol = (warp & 1) * 64;    // 2 warps along n, 64 cols each
    int t4 = lane & 3, g = lane >> 2;

    // loader mapping
    int mA = tid & 127, kgA = (tid >> 7) * 8;   // A (and transB-B): row mA, k-octet kgA
    int n4 = (tid & 31) * 4, kb = tid >> 5;     // normal B: 4-col quad, k row
    bool vecB = (col0 + TBN) <= Nc;

    float acc[2][8][4];
    #pragma unroll
    for (int r = 0; r < 2; r++)
        #pragma unroll
        for (int j = 0; j < 8; j++)
            #pragma unroll
            for (int q = 0; q < 4; q++) acc[r][j][q] = 0.f;

    int nt = K / TBK;

    float4 pa0, pa1, pb0, pb1;
    auto ldg_tile = [&](int k0) {
        pa0 = *(const float4*)&A[(size_t)(row0 + mA) * K + k0 + kgA];
        pa1 = *(const float4*)&A[(size_t)(row0 + mA) * K + k0 + kgA + 4];
        if (transB) {
            pb0 = *(const float4*)&B[(size_t)(col0 + mA) * K + k0 + kgA];
            pb1 = *(const float4*)&B[(size_t)(col0 + mA) * K + k0 + kgA + 4];
        } else {
            int klo = k0 + kb, khi = klo + 8;
            if (vecB) {
                pb0 = *(const float4*)&B[(size_t)klo * Nc + col0 + n4];
                pb1 = *(const float4*)&B[(size_t)khi * Nc + col0 + n4];
            } else {
                float* q0 = &pb0.x; float* q1 = &pb1.x;
                #pragma unroll
                for (int i = 0; i < 4; i++) {
                    int cc = col0 + n4 + i;
                    q0[i] = (cc < Nc) ? B[(size_t)klo * Nc + cc] : 0.f;
                    q1[i] = (cc < Nc) ? B[(size_t)khi * Nc + cc] : 0.f;
                }
            }
            if (dv) {
                float dlo = dv[klo], dhi = dv[khi];
                pb0.x *= dlo; pb0.y *= dlo; pb0.z *= dlo; pb0.w *= dlo;
                pb1.x *= dhi; pb1.y *= dhi; pb1.z *= dhi; pb1.w *= dhi;
            }
        }
    };
    auto sts_tile = [&](int buf) {
        const float* a0 = &pa0.x; const float* a1 = &pa1.x;
        #pragma unroll
        for (int i = 0; i < 4; i++) {
            As[buf][kgA + i    ][mA] = __uint_as_float(to_tf32(a0[i]));
            As[buf][kgA + i + 4][mA] = __uint_as_float(to_tf32(a1[i]));
        }
        const float* b0 = &pb0.x; const float* b1 = &pb1.x;
        if (transB) {
            #pragma unroll
            for (int i = 0; i < 4; i++) {
                Bs[buf][kgA + i    ][mA] = __uint_as_float(to_tf32(b0[i]));
                Bs[buf][kgA + i + 4][mA] = __uint_as_float(to_tf32(b1[i]));
            }
        } else {
            #pragma unroll
            for (int i = 0; i < 4; i++) {
                Bs[buf][kb    ][n4 + i] = __uint_as_float(to_tf32(b0[i]));
                Bs[buf][kb + 8][n4 + i] = __uint_as_float(to_tf32(b1[i]));
            }
        }
    };

    ldg_tile(0);
    sts_tile(0);
    __syncthreads();

    for (int t = 0; t < nt; t++) {
        int buf = t & 1;
        if (t + 1 < nt) ldg_tile((t + 1) * TBK);

        #pragma unroll
        for (int kk = 0; kk < 2; kk++) {
            int klo = kk * 8 + t4;
            int khi = klo + 4;
            uint32_t af[2][4];
            #pragma unroll
            for (int r = 0; r < 2; r++) {
                int m = wrow + r * 16 + g;
                af[r][0] = __float_as_uint(As[buf][klo][m]);
                af[r][1] = __float_as_uint(As[buf][klo][m + 8]);
                af[r][2] = __float_as_uint(As[buf][khi][m]);
                af[r][3] = __float_as_uint(As[buf][khi][m + 8]);
            }
            #pragma unroll
            for (int j = 0; j < 8; j++) {
                int n = wcol + j * 8 + g;
                uint32_t bf[2];
                bf[0] = __float_as_uint(Bs[buf][klo][n]);
                bf[1] = __float_as_uint(Bs[buf][khi][n]);
                mma_tf32(acc[0][j], af[0], bf);
                mma_tf32(acc[1][j], af[1], bf);
            }
        }

        if (t + 1 < nt) sts_tile(buf ^ 1);
        __syncthreads();
    }

    // ---- epilogue ----
    #pragma unroll
    for (int r = 0; r < 2; r++) {
        int rr = row0 + wrow + r * 16 + g;
        float s0 = rsb ? rsb[rr] * alpha : alpha;
        float s1 = rsb ? rsb[rr + 8] * alpha : alpha;
        #pragma unroll
        for (int j = 0; j < 8; j++) {
            int cc = col0 + wcol + j * 8 + t4 * 2;
            float* v = acc[r][j];
            if (expmode) {
                float sr0 = sqb[rr], sr1 = sqb[rr + 8];
                float sc0 = sqb[cc], sc1 = sqb[cc + 1];
                C[(size_t)rr * Nc + cc]           = expf(2.f * v[0] - sr0 - sc0);
                C[(size_t)rr * Nc + cc + 1]       = expf(2.f * v[1] - sr0 - sc1);
                C[(size_t)(rr + 8) * Nc + cc]     = expf(2.f * v[2] - sr1 - sc0);
                C[(size_t)(rr + 8) * Nc + cc + 1] = expf(2.f * v[3] - sr1 - sc1);
            } else {
                #pragma unroll
                for (int h = 0; h < 2; h++) {
                    int rrr = rr + h * 8;
                    float sa = h ? s1 : s0;
                    #pragma unroll
                    for (int q = 0; q < 2; q++) {
                        int ccc = cc + q;
                        if (ccc >= Nc) continue;
                        float w = sa * v[h * 2 + q];
                        if (Cin)  w += beta  * Cin [(size_t)rrr * Nc + ccc];
                        if (Cin2) w += beta2 * Cin2[(size_t)rrr * Nc + ccc];
                        if (bias) w += bias[ccc];
                        if (relu) w = fmaxf(w, 0.f);
                        C[(size_t)rrr * Nc + ccc] = w;
                    }
                }
            }
        }
    }
}

// ---------------- SIMT fallback SGEMM (64x64) — small / K%16!=0 cases ----------------
__global__ void gemm_kernel(const float* __restrict__ A, const float* __restrict__ B,
                            const float* __restrict__ Cin, const float* __restrict__ bias,
                            float* __restrict__ C,
                            int M, int Nc, int K,
                            long long sA, long long sB, long long sCin, long long sC,
                            float alpha, float beta, int relu) {
    int bz = blockIdx.z;
    A += (size_t)bz * sA;
    B += (size_t)bz * sB;
    C += (size_t)bz * sC;
    if (Cin) Cin += (size_t)bz * sCin;

    int row0 = blockIdx.y * 64, col0 = blockIdx.x * 64;
    __shared__ float As[16][65];
    __shared__ float Bs[16][65];
    int tid = threadIdx.y * 16 + threadIdx.x;

    float acc[4][4];
    #pragma unroll
    for (int i = 0; i < 4; i++)
        #pragma unroll
        for (int j = 0; j < 4; j++) acc[i][j] = 0.f;

    for (int k0 = 0; k0 < K; k0 += 16) {
        #pragma unroll
        for (int t = 0; t < 4; t++) {
            int e = tid + t * 256;
            int r = e >> 4, k = e & 15;
            int kk = k0 + k, rr = row0 + r;
            As[k][r] = (kk < K && rr < M) ? A[(size_t)rr * K + kk] : 0.f;
        }
        #pragma unroll
        for (int t = 0; t < 4; t++) {
            int e = tid + t * 256;
            int k = e >> 6, c = e & 63;
            int kk = k0 + k, cc = col0 + c;
            Bs[k][c] = (kk < K && cc < Nc) ? B[(size_t)kk * Nc + cc] : 0.f;
        }
        __syncthreads();
        #pragma unroll
        for (int k = 0; k < 16; k++) {
            float a[4], bv[4];
            #pragma unroll
            for (int i = 0; i < 4; i++) a[i]  = As[k][threadIdx.y * 4 + i];
            #pragma unroll
            for (int j = 0; j < 4; j++) bv[j] = Bs[k][threadIdx.x * 4 + j];
            #pragma unroll
            for (int i = 0; i < 4; i++)
                #pragma unroll
                for (int j = 0; j < 4; j++) acc[i][j] += a[i] * bv[j];
        }
        __syncthreads();
    }

    #pragma unroll
    for (int i = 0; i < 4; i++) {
        int r = row0 + threadIdx.y * 4 + i;
        if (r >= M) continue;
        #pragma unroll
        for (int j = 0; j < 4; j++) {
            int c = col0 + threadIdx.x * 4 + j;
            if (c >= Nc) continue;
            float v = alpha * acc[i][j];
            if (Cin)  v += beta * Cin[(size_t)r * Nc + c];
            if (bias) v += bias[c];
            if (relu) v = fmaxf(v, 0.f);
            C[(size_t)r * Nc + c] = v;
        }
    }
}

// ---------------- global max pool over n (float4 over features) ----------------
__global__ void maxpool_kernel(const float4* __restrict__ X, float4* __restrict__ out) {
    int f4 = blockIdx.x * blockDim.x + threadIdx.x;
    int b = blockIdx.y;
    if (f4 >= F3 / 4) return;
    const float4* p = X + (size_t)b * NN * (F3 / 4) + f4;
    float4 m = make_float4(-INFINITY, -INFINITY, -INFINITY, -INFINITY);
    for (int n = 0; n < NN; n++) {
        float4 v = p[(size_t)n * (F3 / 4)];
        m.x = fmaxf(m.x, v.x); m.y = fmaxf(m.y, v.y);
        m.z = fmaxf(m.z, v.z); m.w = fmaxf(m.w, v.w);
    }
    out[b * (F3 / 4) + f4] = m;
}

// ---------------- host orchestration ----------------
static void run_gemm64(const float* A, const float* B, const float* Cin, const float* bias,
                       float* C, int M, int Nc, int K,
                       long long sA, long long sB, long long sCin, long long sC,
                       float alpha, float beta, int relu, int batch) {
    dim3 grid((Nc + 63) / 64, (M + 63) / 64, batch);
    gemm_kernel<<<grid, dim3(16, 16)>>>(A, B, Cin, bias, C, M, Nc, K,
                                        sA, sB, sCin, sC, alpha, beta, relu);
}

static void run_tgemm(const float* A, const float* B, const float* Cin, const float* Cin2,
                      const float* bias, const float* sqv, const float* rs, const float* dvec,
                      float* C, int Nc, int K,
                      long long sA, long long sB, long long sCin, long long sCin2, long long sC,
                      float alpha, float beta, float beta2, int relu, int expmode, int transB) {
    dim3 grid((Nc + TBN - 1) / TBN, NN / TBM, BB);
    tgemm_kernel<<<grid, 256>>>(A, B, Cin, Cin2, bias, sqv, rs, dvec, C, Nc, K,
                                sA, sB, sCin, sCin2, sC,
                                alpha, beta, beta2, relu, expmode, transB);
}

static void run_layer(const float* xin, int Fin, int Fout,
                      const float* W, const float* bias, float* xout,
                      float* Aadj, float* sq, float* dis, float* t1, float* t2) {
    long long sNF = (long long)NN * Fin;
    long long sLL = (long long)NN * NN;
    long long sNO = (long long)NN * Fout;
    bool tc = (Fin % 16) == 0;

    rowsq_kernel<<<BB * NN / 8, 256>>>(xin, sq, Fin);
    if (tc) {
        run_tgemm(xin, xin, nullptr, nullptr, nullptr, sq, nullptr, nullptr,
                  Aadj, NN, Fin, sNF, sNF, 0, 0, sLL,
                  1.f, 0.f, 0.f, 0, 1, 1);
    } else {
        gram_exp_kernel<<<dim3(NN / 64, NN / 64, BB), dim3(16, 16)>>>(xin, sq, Aadj, Fin);
    }
    deg_kernel<<<BB * NN / 8, 256>>>(Aadj, dis);
    // normalization folded into the GEMMs: L@v = v - dn .* (A @ (dm .* v))

    // t1 = L @ xin = xin - dn.*(A@(dm.*xin))
    run_tgemm(Aadj, xin, xin, nullptr, nullptr, nullptr, dis, dis,
              t1, Fin, NN, sLL, sNF, sNF, 0, sNF,
              -1.f, 1.f, 0.f, 0, 0, 0);
    // t2 = 2 L@t1 - xin = -2*dn.*(A@(dm.*t1)) + 2*t1 - xin
    run_tgemm(Aadj, t1, t1, xin, nullptr, nullptr, dis, dis,
              t2, Fin, NN, sLL, sNF, sNF, sNF, sNF,
              -2.f, 2.f, -1.f, 0, 0, 0);

    if (tc) {
        run_tgemm(xin, W, nullptr, nullptr, nullptr, nullptr, nullptr, nullptr,
                  xout, Fout, Fin, sNF, 0, 0, 0, sNO,
                  1.f, 0.f, 0.f, 0, 0, 0);
        run_tgemm(t1, W + (size_t)Fin * Fout, xout, nullptr, nullptr, nullptr, nullptr, nullptr,
                  xout, Fout, Fin, sNF, 0, sNO, 0, sNO,
                  1.f, 1.f, 0.f, 0, 0, 0);
        run_tgemm(t2, W + 2 * (size_t)Fin * Fout, xout, nullptr, bias, nullptr, nullptr, nullptr,
                  xout, Fout, Fin, sNF, 0, sNO, 0, sNO,
                  1.f, 1.f, 0.f, 1, 0, 0);
    } else {
        run_gemm64(xin, W, nullptr, nullptr, xout, NN, Fout, Fin,
                   sNF, 0, 0, sNO, 1.f, 0.f, 0, BB);
        run_gemm64(t1, W + (size_t)Fin * Fout, xout, nullptr, xout, NN, Fout, Fin,
                   sNF, 0, sNO, sNO, 1.f, 1.f, 0, BB);
        run_gemm64(t2, W + 2 * (size_t)Fin * Fout, xout, bias, xout, NN, Fout, Fin,
                   sNF, 0, sNO, sNO, 1.f, 1.f, 1, BB);
    }
}

extern "C" void kernel_launch(void* const* d_in, const int* in_sizes, int n_in,
                              void* d_out, int out_size) {
    const float* x     = (const float*)d_in[0];
    const float* W1    = (const float*)d_in[1];
    const float* b1    = (const float*)d_in[2];
    const float* W2    = (const float*)d_in[3];
    const float* b2    = (const float*)d_in[4];
    const float* W3    = (const float*)d_in[5];
    const float* b3    = (const float*)d_in[6];
    const float* fc1_w = (const float*)d_in[7];
    const float* fc1_b = (const float*)d_in[8];
    const float* fc2_w = (const float*)d_in[9];
    const float* fc2_b = (const float*)d_in[10];
    const float* fc3_w = (const float*)d_in[11];
    const float* fc3_b = (const float*)d_in[12];

    float *Aadj, *feat, *mid, *t1, *t2, *sq, *dis, *pool, *fc1b, *fc2b;
    cudaGetSymbolAddress((void**)&Aadj, g_A);
    cudaGetSymbolAddress((void**)&feat, g_feat);
    cudaGetSymbolAddress((void**)&mid,  g_mid);
    cudaGetSymbolAddress((void**)&t1,   g_t1);
    cudaGetSymbolAddress((void**)&t2,   g_t2);
    cudaGetSymbolAddress((void**)&sq,   g_sq);
    cudaGetSymbolAddress((void**)&dis,  g_dis);
    cudaGetSymbolAddress((void**)&pool, g_pool);
    cudaGetSymbolAddress((void**)&fc1b, g_fc1);
    cudaGetSymbolAddress((void**)&fc2b, g_fc2);

    // three Chebyshev graph-conv layers
    run_layer(x,    FIN, F1, W1, b1, feat, Aadj, sq, dis, t1, t2);   // [B,N,128]
    run_layer(feat, F1,  F2, W2, b2, mid,  Aadj, sq, dis, t1, t2);   // [B,N,512]
    run_layer(mid,  F2,  F3, W3, b3, feat, Aadj, sq, dis, t1, t2);   // [B,N,1024]

    // global max pool
    maxpool_kernel<<<dim3((F3 / 4 + 255) / 256, BB), 256>>>((const float4*)feat, (float4*)pool);

    // FC head (tiny — SIMT)
    run_gemm64(pool, fc1_w, nullptr, fc1_b, fc1b, BB, 512, 1024, 0, 0, 0, 0, 1.f, 0.f, 1, 1);
    run_gemm64(fc1b, fc2_w, nullptr, fc2_b, fc2b, BB, 128, 512,  0, 0, 0, 0, 1.f, 0.f, 1, 1);
    run_gemm64(fc2b, fc3_w, nullptr, fc3_b, (float*)d_out, BB, CLS, 128,
               0, 0, 0, 0, 1.f, 0.f, 0, 1);
}

// round 12
// speedup vs baseline: 1.5495x; 1.5495x over previous
#include <cuda_runtime.h>
#include <math.h>
#include <stdint.h>

#define BB  32
#define NN  1024
#define FIN 6
#define F1  128
#define F2  512
#define F3  1024
#define CLS 40

#define TBM 128
#define TBN 128
#define TBK 16
#define TPAD 8

// ---------------- scratch (static __device__ — no allocation allowed) ----------------
__device__ float g_A   [(size_t)BB * NN * NN];   // adjacency exp(-d2), 128 MB
__device__ float g_feat[(size_t)BB * NN * F3];
__device__ float g_mid [(size_t)BB * NN * F2];
__device__ float g_t1  [(size_t)BB * NN * F2];
__device__ float g_t2  [(size_t)BB * NN * F2];
__device__ float g_sq  [BB * NN];
__device__ float g_dis [BB * NN];
__device__ float g_pool[BB * F3];
__device__ float g_fc1 [BB * 512];
__device__ float g_fc2 [BB * 128];

// ---------------- tf32 helpers ----------------
__device__ __forceinline__ float tf32f(float x) {
    uint32_t r;
    asm("cvt.rna.tf32.f32 %0, %1;" : "=r"(r) : "f"(x));
    return __uint_as_float(r);
}
__device__ __forceinline__ void mma_tf32(float* c, const uint32_t* a, const uint32_t* b) {
    asm volatile(
        "mma.sync.aligned.m16n8k8.row.col.f32.tf32.tf32.f32 "
        "{%0,%1,%2,%3}, {%4,%5,%6,%7}, {%8,%9}, {%0,%1,%2,%3};"
        : "+f"(c[0]), "+f"(c[1]), "+f"(c[2]), "+f"(c[3])
        : "r"(a[0]), "r"(a[1]), "r"(a[2]), "r"(a[3]), "r"(b[0]), "r"(b[1]));
}

// ---------------- row squared-norms ----------------
__global__ void rowsq_kernel(const float* __restrict__ x, float* __restrict__ sq, int F) {
    int row  = blockIdx.x * (blockDim.x / 32) + (threadIdx.x >> 5);
    int lane = threadIdx.x & 31;
    if (row >= BB * NN) return;
    const float* p = x + (size_t)row * F;
    float s = 0.f;
    for (int f = lane; f < F; f += 32) { float v = p[f]; s += v * v; }
    #pragma unroll
    for (int o = 16; o; o >>= 1) s += __shfl_down_sync(0xffffffffu, s, o);
    if (lane == 0) sq[row] = s;
}

// ---------------- SIMT gram (F=6): A = exp(2<x_n,x_m> - sq_n - sq_m) ----------------
__global__ void gram_exp_kernel(const float* __restrict__ X, const float* __restrict__ sq,
                                float* __restrict__ Aout, int F) {
    int b = blockIdx.z;
    const float* Xb  = X    + (size_t)b * NN * F;
    float*       Ab  = Aout + (size_t)b * NN * NN;
    const float* sqb = sq   + b * NN;

    int row0 = blockIdx.y * 64, col0 = blockIdx.x * 64;
    __shared__ float As[16][65];
    __shared__ float Bs[16][65];
    int tid = threadIdx.y * 16 + threadIdx.x;

    float acc[4][4];
    #pragma unroll
    for (int i = 0; i < 4; i++)
        #pragma unroll
        for (int j = 0; j < 4; j++) acc[i][j] = 0.f;

    for (int k0 = 0; k0 < F; k0 += 16) {
        #pragma unroll
        for (int t = 0; t < 4; t++) {
            int e = tid + t * 256;
            int r = e >> 4, k = e & 15;
            int kk = k0 + k;
            As[k][r] = (kk < F) ? Xb[(size_t)(row0 + r) * F + kk] : 0.f;
        }
        #pragma unroll
        for (int t = 0; t < 4; t++) {
            int e = tid + t * 256;
            int c = e >> 4, k = e & 15;
            int kk = k0 + k;
            Bs[k][c] = (kk < F) ? Xb[(size_t)(col0 + c) * F + kk] : 0.f;
        }
        __syncthreads();
        #pragma unroll
        for (int k = 0; k < 16; k++) {
            float a[4], bv[4];
            #pragma unroll
            for (int i = 0; i < 4; i++) a[i]  = As[k][threadIdx.y * 4 + i];
            #pragma unroll
            for (int j = 0; j < 4; j++) bv[j] = Bs[k][threadIdx.x * 4 + j];
            #pragma unroll
            for (int i = 0; i < 4; i++)
                #pragma unroll
                for (int j = 0; j < 4; j++) acc[i][j] += a[i] * bv[j];
        }
        __syncthreads();
    }

    #pragma unroll
    for (int i = 0; i < 4; i++) {
        int r = row0 + threadIdx.y * 4 + i;
        float sr = sqb[r];
        #pragma unroll
        for (int j = 0; j < 4; j++) {
            int c = col0 + threadIdx.x * 4 + j;
            Ab[(size_t)r * NN + c] = expf(2.f * acc[i][j] - sr - sqb[c]);
        }
    }
}

// ---------------- dis[b,n] = 1/sqrt(sum_m A[b,n,m]) — float4 reads ----------------
__global__ void deg_kernel(const float* __restrict__ A, float* __restrict__ dis) {
    int row  = blockIdx.x * (blockDim.x / 32) + (threadIdx.x >> 5);
    int lane = threadIdx.x & 31;
    if (row >= BB * NN) return;
    const float4* p = (const float4*)(A + (size_t)row * NN);
    float s = 0.f;
    for (int m = lane; m < NN / 4; m += 32) {
        float4 v = p[m];
        s += v.x + v.y + v.z + v.w;
    }
    #pragma unroll
    for (int o = 16; o; o >>= 1) s += __shfl_down_sync(0xffffffffu, s, o);
    if (lane == 0) dis[row] = 1.f / sqrtf(s);
}

// ---------------- small-F L-apply (layer 1, F=FIN=6), row per warp ----------------
// out[n,:] = alpha * dn[n] * (A[n,:] @ (dm .* v)) + beta*r1[n,:] + beta2*r2[n,:]
__global__ void smallLx_kernel(const float* __restrict__ A, const float* __restrict__ v,
                               const float* __restrict__ r1, const float* __restrict__ r2,
                               const float* __restrict__ dis, float* __restrict__ out,
                               float alpha, float beta, float beta2) {
    int row  = blockIdx.x * (blockDim.x / 32) + (threadIdx.x >> 5);
    int lane = threadIdx.x & 31;
    if (row >= BB * NN) return;
    int b = row >> 10;
    const float*  Ar = A   + (size_t)row * NN;
    const float*  db = dis + (size_t)b * NN;
    const float*  vb = v   + (size_t)b * NN * FIN;

    float acc[FIN];
    #pragma unroll
    for (int f = 0; f < FIN; f++) acc[f] = 0.f;

    for (int m = lane; m < NN; m += 32) {
        float w = Ar[m] * db[m];
        const float* vp = vb + (size_t)m * FIN;
        #pragma unroll
        for (int f = 0; f < FIN; f++) acc[f] += w * vp[f];
    }
    #pragma unroll
    for (int f = 0; f < FIN; f++) {
        #pragma unroll
        for (int o = 16; o; o >>= 1) acc[f] += __shfl_down_sync(0xffffffffu, acc[f], o);
    }
    if (lane == 0) {
        float dn = db[row & 1023];
        #pragma unroll
        for (int f = 0; f < FIN; f++) {
            float w = alpha * dn * acc[f] + beta * r1[(size_t)row * FIN + f];
            if (r2) w += beta2 * r2[(size_t)row * FIN + f];
            out[(size_t)row * FIN + f] = w;
        }
    }
}

// ---------------- tf32 tensor-core GEMM ----------------
// A operand: if A1 != null, logical A = [A|A1|A2] along k, each segment Fseg wide
//            (Fseg multiple of 8); else plain [1024, K].
// acc = A @ B'  where B' = (dvec ? diag(dvec) : I) @ B
// epilogue:
//   expmode: C = exp(2*acc - sq_r - sq_c)
//   else:    C = (rs ? rs[r] : 1)*alpha*acc + beta*Cin + beta2*Cin2 + bias, opt. relu
__global__ __launch_bounds__(256) void tgemm_kernel(
    const float* __restrict__ A, const float* __restrict__ A1, const float* __restrict__ A2,
    const float* __restrict__ B,
    const float* __restrict__ Cin, const float* __restrict__ Cin2,
    const float* __restrict__ bias,
    const float* __restrict__ sqv, const float* __restrict__ rs,
    const float* __restrict__ dvec,
    float* __restrict__ C,
    int Nc, int K, int Fseg,
    long long sA, long long sB, long long sCin, long long sCin2, long long sC,
    float alpha, float beta, float beta2, int relu, int expmode, int transB)
{
    int bz = blockIdx.z;
    A += (size_t)bz * sA;
    if (A1) { A1 += (size_t)bz * sA; A2 += (size_t)bz * sA; }
    B += (size_t)bz * sB;
    C += (size_t)bz * sC;
    if (Cin)  Cin  += (size_t)bz * sCin;
    if (Cin2) Cin2 += (size_t)bz * sCin2;
    const float* sqb = sqv  ? (sqv  + (size_t)bz * NN) : nullptr;
    const float* rsb = rs   ? (rs   + (size_t)bz * NN) : nullptr;
    const float* dv  = dvec ? (dvec + (size_t)bz * NN) : nullptr;

    int row0 = blockIdx.y * TBM, col0 = blockIdx.x * TBN;

    __shared__ float As[2][TBK][TBM + TPAD];
    __shared__ float Bs[2][TBK][TBN + TPAD];

    int tid  = threadIdx.x;
    int lane = tid & 31;
    int warp = tid >> 5;
    int wrow = (warp >> 1) * 32;
    int wcol = (warp & 1) * 64;
    int t4 = lane & 3, g = lane >> 2;

    int mA = tid & 127, kgA = (tid >> 7) * 8;   // A / transB-B loader
    int n4 = (tid & 31) * 4, kb = tid >> 5;     // normal-B loader
    bool vecB = (col0 + TBN) <= Nc;

    float acc[2][8][4];
    #pragma unroll
    for (int r = 0; r < 2; r++)
        #pragma unroll
        for (int j = 0; j < 8; j++)
            #pragma unroll
            for (int q = 0; q < 4; q++) acc[r][j][q] = 0.f;

    int nt = K / TBK;

    float4 pa0, pa1, pb0, pb1;
    auto ldg_tile = [&](int k0) {
        int kk = k0 + kgA;
        const float* ap;
        int kw;
        if (A1) {
            int seg = (kk >= 2 * Fseg) ? 2 : (kk >= Fseg ? 1 : 0);
            ap = (seg == 0) ? A : (seg == 1 ? A1 : A2);
            kw = Fseg;
            kk -= seg * Fseg;
        } else { ap = A; kw = K; }
        pa0 = *(const float4*)&ap[(size_t)(row0 + mA) * kw + kk];
        pa1 = *(const float4*)&ap[(size_t)(row0 + mA) * kw + kk + 4];
        if (transB) {
            pb0 = *(const float4*)&B[(size_t)(col0 + mA) * K + k0 + kgA];
            pb1 = *(const float4*)&B[(size_t)(col0 + mA) * K + k0 + kgA + 4];
        } else {
            int klo = k0 + kb, khi = klo + 8;
            if (vecB) {
                pb0 = *(const float4*)&B[(size_t)klo * Nc + col0 + n4];
                pb1 = *(const float4*)&B[(size_t)khi * Nc + col0 + n4];
            } else {
                float* q0 = &pb0.x; float* q1 = &pb1.x;
                #pragma unroll
                for (int i = 0; i < 4; i++) {
                    int cc = col0 + n4 + i;
                    q0[i] = (cc < Nc) ? B[(size_t)klo * Nc + cc] : 0.f;
                    q1[i] = (cc < Nc) ? B[(size_t)khi * Nc + cc] : 0.f;
                }
            }
            if (dv) {
                float dlo = dv[klo], dhi = dv[khi];
                pb0.x *= dlo; pb0.y *= dlo; pb0.z *= dlo; pb0.w *= dlo;
                pb1.x *= dhi; pb1.y *= dhi; pb1.z *= dhi; pb1.w *= dhi;
            }
        }
    };
    auto sts_tile = [&](int buf) {
        const float* a0 = &pa0.x; const float* a1 = &pa1.x;
        #pragma unroll
        for (int i = 0; i < 4; i++) {
            As[buf][kgA + i    ][mA] = tf32f(a0[i]);
            As[buf][kgA + i + 4][mA] = tf32f(a1[i]);
        }
        const float* b0 = &pb0.x; const float* b1 = &pb1.x;
        if (transB) {
            #pragma unroll
            for (int i = 0; i < 4; i++) {
                Bs[buf][kgA + i    ][mA] = tf32f(b0[i]);
                Bs[buf][kgA + i + 4][mA] = tf32f(b1[i]);
            }
        } else {
            #pragma unroll
            for (int i = 0; i < 4; i++) {
                Bs[buf][kb    ][n4 + i] = tf32f(b0[i]);
                Bs[buf][kb + 8][n4 + i] = tf32f(b1[i]);
            }
        }
    };

    ldg_tile(0);
    sts_tile(0);
    __syncthreads();

    for (int t = 0; t < nt; t++) {
        int buf = t & 1;
        if (t + 1 < nt) ldg_tile((t + 1) * TBK);

        #pragma unroll
        for (int kk = 0; kk < 2; kk++) {
            int klo = kk * 8 + t4;
            int khi = klo + 4;
            uint32_t af[2][4];
            #pragma unroll
            for (int r = 0; r < 2; r++) {
                int m = wrow + r * 16 + g;
                af[r][0] = __float_as_uint(As[buf][klo][m]);
                af[r][1] = __float_as_uint(As[buf][klo][m + 8]);
                af[r][2] = __float_as_uint(As[buf][khi][m]);
                af[r][3] = __float_as_uint(As[buf][khi][m + 8]);
            }
            #pragma unroll
            for (int j = 0; j < 8; j++) {
                int n = wcol + j * 8 + g;
                uint32_t bf[2];
                bf[0] = __float_as_uint(Bs[buf][klo][n]);
                bf[1] = __float_as_uint(Bs[buf][khi][n]);
                mma_tf32(acc[0][j], af[0], bf);
                mma_tf32(acc[1][j], af[1], bf);
            }
        }

        if (t + 1 < nt) sts_tile(buf ^ 1);
        __syncthreads();
    }

    // ---- epilogue ----
    #pragma unroll
    for (int r = 0; r < 2; r++) {
        int rr = row0 + wrow + r * 16 + g;
        float s0 = rsb ? rsb[rr] * alpha : alpha;
        float s1 = rsb ? rsb[rr + 8] * alpha : alpha;
        #pragma unroll
        for (int j = 0; j < 8; j++) {
            int cc = col0 + wcol + j * 8 + t4 * 2;
            float* v = acc[r][j];
            if (expmode) {
                float sr0 = sqb[rr], sr1 = sqb[rr + 8];
                float sc0 = sqb[cc], sc1 = sqb[cc + 1];
                C[(size_t)rr * Nc + cc]           = expf(2.f * v[0] - sr0 - sc0);
                C[(size_t)rr * Nc + cc + 1]       = expf(2.f * v[1] - sr0 - sc1);
                C[(size_t)(rr + 8) * Nc + cc]     = expf(2.f * v[2] - sr1 - sc0);
                C[(size_t)(rr + 8) * Nc + cc + 1] = expf(2.f * v[3] - sr1 - sc1);
            } else {
                #pragma unroll
                for (int h = 0; h < 2; h++) {
                    int rrr = rr + h * 8;
                    float sa = h ? s1 : s0;
                    #pragma unroll
                    for (int q = 0; q < 2; q++) {
                        int ccc = cc + q;
                        if (ccc >= Nc) continue;
                        float w = sa * v[h * 2 + q];
                        if (Cin)  w += beta  * Cin [(size_t)rrr * Nc + ccc];
                        if (Cin2) w += beta2 * Cin2[(size_t)rrr * Nc + ccc];
                        if (bias) w += bias[ccc];
                        if (relu) w = fmaxf(w, 0.f);
                        C[(size_t)rrr * Nc + ccc] = w;
                    }
                }
            }
        }
    }
}

// ---------------- SIMT fallback SGEMM (64x64) — small / K%16!=0 cases ----------------
__global__ void gemm_kernel(const float* __restrict__ A, const float* __restrict__ B,
                            const float* __restrict__ Cin, const float* __restrict__ bias,
                            float* __restrict__ C,
                            int M, int Nc, int K,
                            long long sA, long long sB, long long sCin, long long sC,
                            float alpha, float beta, int relu) {
    int bz = blockIdx.z;
    A += (size_t)bz * sA;
    B += (size_t)bz * sB;
    C += (size_t)bz * sC;
    if (Cin) Cin += (size_t)bz * sCin;

    int row0 = blockIdx.y * 64, col0 = blockIdx.x * 64;
    __shared__ float As[16][65];
    __shared__ float Bs[16][65];
    int tid = threadIdx.y * 16 + threadIdx.x;

    float acc[4][4];
    #pragma unroll
    for (int i = 0; i < 4; i++)
        #pragma unroll
        for (int j = 0; j < 4; j++) acc[i][j] = 0.f;

    for (int k0 = 0; k0 < K; k0 += 16) {
        #pragma unroll
        for (int t = 0; t < 4; t++) {
            int e = tid + t * 256;
            int r = e >> 4, k = e & 15;
            int kk = k0 + k, rr = row0 + r;
            As[k][r] = (kk < K && rr < M) ? A[(size_t)rr * K + kk] : 0.f;
        }
        #pragma unroll
        for (int t = 0; t < 4; t++) {
            int e = tid + t * 256;
            int k = e >> 6, c = e & 63;
            int kk = k0 + k, cc = col0 + c;
            Bs[k][c] = (kk < K && cc < Nc) ? B[(size_t)kk * Nc + cc] : 0.f;
        }
        __syncthreads();
        #pragma unroll
        for (int k = 0; k < 16; k++) {
            float a[4], bv[4];
            #pragma unroll
            for (int i = 0; i < 4; i++) a[i]  = As[k][threadIdx.y * 4 + i];
            #pragma unroll
            for (int j = 0; j < 4; j++) bv[j] = Bs[k][threadIdx.x * 4 + j];
            #pragma unroll
            for (int i = 0; i < 4; i++)
                #pragma unroll
                for (int j = 0; j < 4; j++) acc[i][j] += a[i] * bv[j];
        }
        __syncthreads();
    }

    #pragma unroll
    for (int i = 0; i < 4; i++) {
        int r = row0 + threadIdx.y * 4 + i;
        if (r >= M) continue;
        #pragma unroll
        for (int j = 0; j < 4; j++) {
            int c = col0 + threadIdx.x * 4 + j;
            if (c >= Nc) continue;
            float v = alpha * acc[i][j];
            if (Cin)  v += beta * Cin[(size_t)r * Nc + c];
            if (bias) v += bias[c];
            if (relu) v = fmaxf(v, 0.f);
            C[(size_t)r * Nc + c] = v;
        }
    }
}

// ---------------- global max pool over n (float4 over features) ----------------
__global__ void maxpool_kernel(const float4* __restrict__ X, float4* __restrict__ out) {
    int f4 = blockIdx.x * blockDim.x + threadIdx.x;
    int b = blockIdx.y;
    if (f4 >= F3 / 4) return;
    const float4* p = X + (size_t)b * NN * (F3 / 4) + f4;
    float4 m = make_float4(-INFINITY, -INFINITY, -INFINITY, -INFINITY);
    for (int n = 0; n < NN; n++) {
        float4 v = p[(size_t)n * (F3 / 4)];
        m.x = fmaxf(m.x, v.x); m.y = fmaxf(m.y, v.y);
        m.z = fmaxf(m.z, v.z); m.w = fmaxf(m.w, v.w);
    }
    out[b * (F3 / 4) + f4] = m;
}

// ---------------- host orchestration ----------------
static void run_gemm64(const float* A, const float* B, const float* Cin, const float* bias,
                       float* C, int M, int Nc, int K,
                       long long sA, long long sB, long long sCin, long long sC,
                       float alpha, float beta, int relu, int batch) {
    dim3 grid((Nc + 63) / 64, (M + 63) / 64, batch);
    gemm_kernel<<<grid, dim3(16, 16)>>>(A, B, Cin, bias, C, M, Nc, K,
                                        sA, sB, sCin, sC, alpha, beta, relu);
}

static void run_tgemm(const float* A, const float* A1, const float* A2, const float* B,
                      const float* Cin, const float* Cin2,
                      const float* bias, const float* sqv, const float* rs, const float* dvec,
                      float* C, int Nc, int K, int Fseg,
                      long long sA, long long sB, long long sCin, long long sCin2, long long sC,
                      float alpha, float beta, float beta2, int relu, int expmode, int transB) {
    dim3 grid((Nc + TBN - 1) / TBN, NN / TBM, BB);
    tgemm_kernel<<<grid, 256>>>(A, A1, A2, B, Cin, Cin2, bias, sqv, rs, dvec, C, Nc, K, Fseg,
                                sA, sB, sCin, sCin2, sC,
                                alpha, beta, beta2, relu, expmode, transB);
}

static void run_layer(const float* xin, int Fin, int Fout,
                      const float* W, const float* bias, float* xout,
                      float* Aadj, float* sq, float* dis, float* t1, float* t2) {
    long long sNF = (long long)NN * Fin;
    long long sLL = (long long)NN * NN;
    long long sNO = (long long)NN * Fout;
    bool tc = (Fin % 16) == 0;

    rowsq_kernel<<<BB * NN / 8, 256>>>(xin, sq, Fin);
    if (tc) {
        run_tgemm(xin, nullptr, nullptr, xin, nullptr, nullptr, nullptr, sq, nullptr, nullptr,
                  Aadj, NN, Fin, 0, sNF, sNF, 0, 0, sLL,
                  1.f, 0.f, 0.f, 0, 1, 1);
    } else {
        gram_exp_kernel<<<dim3(NN / 64, NN / 64, BB), dim3(16, 16)>>>(xin, sq, Aadj, Fin);
    }
    deg_kernel<<<BB * NN / 8, 256>>>(Aadj, dis);
    // normalization folded: L@v = v - dn .* (A @ (dm .* v))

    if (tc) {
        // t1 = xin - dn.*(A@(dm.*xin))
        run_tgemm(Aadj, nullptr, nullptr, xin, xin, nullptr, nullptr, nullptr, dis, dis,
                  t1, Fin, NN, 0, sLL, sNF, sNF, 0, sNF,
                  -1.f, 1.f, 0.f, 0, 0, 0);
        // t2 = -2*dn.*(A@(dm.*t1)) + 2*t1 - xin
        run_tgemm(Aadj, nullptr, nullptr, t1, t1, xin, nullptr, nullptr, dis, dis,
                  t2, Fin, NN, 0, sLL, sNF, sNF, sNF, sNF,
                  -2.f, 2.f, -1.f, 0, 0, 0);
        // fused: xout = relu([xin|t1|t2] @ [W0;W1;W2] + bias)
        run_tgemm(xin, t1, t2, W, nullptr, nullptr, bias, nullptr, nullptr, nullptr,
                  xout, Fout, 3 * Fin, Fin, sNF, 0, 0, 0, sNO,
                  1.f, 0.f, 0.f, 1, 0, 0);
    } else {
        // layer 1: specialized small-F path (F = FIN = 6)
        smallLx_kernel<<<BB * NN / 8, 256>>>(Aadj, xin, xin, nullptr, dis, t1, -1.f, 1.f, 0.f);
        smallLx_kernel<<<BB * NN / 8, 256>>>(Aadj, t1, t1, xin, dis, t2, -2.f, 2.f, -1.f);
        run_gemm64(xin, W, nullptr, nullptr, xout, NN, Fout, Fin,
                   sNF, 0, 0, sNO, 1.f, 0.f, 0, BB);
        run_gemm64(t1, W + (size_t)Fin * Fout, xout, nullptr, xout, NN, Fout, Fin,
                   sNF, 0, sNO, sNO, 1.f, 1.f, 0, BB);
        run_gemm64(t2, W + 2 * (size_t)Fin * Fout, xout, bias, xout, NN, Fout, Fin,
                   sNF, 0, sNO, sNO, 1.f, 1.f, 1, BB);
    }
}

extern "C" void kernel_launch(void* const* d_in, const int* in_sizes, int n_in,
                              void* d_out, int out_size) {
    const float* x     = (const float*)d_in[0];
    const float* W1    = (const float*)d_in[1];
    const float* b1    = (const float*)d_in[2];
    const float* W2    = (const float*)d_in[3];
    const float* b2    = (const float*)d_in[4];
    const float* W3    = (const float*)d_in[5];
    const float* b3    = (const float*)d_in[6];
    const float* fc1_w = (const float*)d_in[7];
    const float* fc1_b = (const float*)d_in[8];
    const float* fc2_w = (const float*)d_in[9];
    const float* fc2_b = (const float*)d_in[10];
    const float* fc3_w = (const float*)d_in[11];
    const float* fc3_b = (const float*)d_in[12];

    float *Aadj, *feat, *mid, *t1, *t2, *sq, *dis, *pool, *fc1b, *fc2b;
    cudaGetSymbolAddress((void**)&Aadj, g_A);
    cudaGetSymbolAddress((void**)&feat, g_feat);
    cudaGetSymbolAddress((void**)&mid,  g_mid);
    cudaGetSymbolAddress((void**)&t1,   g_t1);
    cudaGetSymbolAddress((void**)&t2,   g_t2);
    cudaGetSymbolAddress((void**)&sq,   g_sq);
    cudaGetSymbolAddress((void**)&dis,  g_dis);
    cudaGetSymbolAddress((void**)&pool, g_pool);
    cudaGetSymbolAddress((void**)&fc1b, g_fc1);
    cudaGetSymbolAddress((void**)&fc2b, g_fc2);

    // three Chebyshev graph-conv layers
    run_layer(x,    FIN, F1, W1, b1, feat, Aadj, sq, dis, t1, t2);   // [B,N,128]
    run_layer(feat, F1,  F2, W2, b2, mid,  Aadj, sq, dis, t1, t2);   // [B,N,512]
    run_layer(mid,  F2,  F3, W3, b3, feat, Aadj, sq, dis, t1, t2);   // [B,N,1024]

    // global max pool
    maxpool_kernel<<<dim3((F3 / 4 + 255) / 256, BB), 256>>>((const float4*)feat, (float4*)pool);

    // FC head (tiny — SIMT)
    run_gemm64(pool, fc1_w, nullptr, fc1_b, fc1b, BB, 512, 1024, 0, 0, 0, 0, 1.f, 0.f, 1, 1);
    run_gemm64(fc1b, fc2_w, nullptr, fc2_b, fc2b, BB, 128, 512,  0, 0, 0, 0, 1.f, 0.f, 1, 1);
    run_gemm64(fc2b, fc3_w, nullptr, fc3_b, (float*)d_out, BB, CLS, 128,
               0, 0, 0, 0, 1.f, 0.f, 0, 1);
}